// round 15
// baseline (speedup 1.0000x reference)
#include <cuda_runtime.h>
#include <cuda_fp16.h>
#include <cstdint>
#include <math.h>

#define Bk 8
#define Lk 2048
#define Dk 2048
#define Rk 256
#define BLk (Bk * Lk)   // 16384 rows

// ---------------- device scratch ----------------
static __device__ float g_E[Rk * Rk];                 // E = C @ dlt fp32  (256x256)
static __device__ __half g_Eh[Rk * Rk];               // E fp16
static __device__ __half g_Ph[Dk * Rk];               // P fp16 (d-major, r-contig)
static __device__ __half g_BT1[Rk * Dk];              // A'^T fp16         (256x2048)
static __device__ __half g_WqT[Dk * Rk];              // Wq^T fp16         (2048x256)
static __device__ __half g_U[(size_t)BLk * Rk];       // z_mixed fp16
static __device__ float g_feat[BLk];
static __device__ float g_pg[Rk], g_pb[Rk];
static __device__ float g_cA[Rk], g_cB[Rk];
static __device__ float g_G[Dk];
static __device__ float g_consts[4];
static __device__ float g_pgp[32 * Rk], g_pbp[32 * Rk];

// ---------------- helpers ----------------
__device__ __forceinline__ uint32_t smem_u32(const void* p) {
    uint32_t a;
    asm("{ .reg .u64 t; cvta.to.shared.u64 t, %1; cvt.u32.u64 %0, t; }" : "=r"(a) : "l"(p));
    return a;
}
__device__ __forceinline__ void cp16(void* dst, const void* src) {
    uint32_t d = smem_u32(dst);
    asm volatile("cp.async.cg.shared.global [%0], [%1], 16;" :: "r"(d), "l"(src) : "memory");
}
#define CP_COMMIT() asm volatile("cp.async.commit_group;" ::: "memory")
#define CP_WAIT0()  asm volatile("cp.async.wait_group 0;" ::: "memory")
#define CP_WAIT1()  asm volatile("cp.async.wait_group 1;" ::: "memory")

#define LDSM4(r0, r1, r2, r3, addr) \
    asm volatile("ldmatrix.sync.aligned.m8n8.x4.shared.b16 {%0,%1,%2,%3}, [%4];" \
        : "=r"(r0), "=r"(r1), "=r"(r2), "=r"(r3) : "r"(addr))

#define MMAF16(c, a, b) \
    asm volatile( \
        "mma.sync.aligned.m16n8k16.row.col.f32.f16.f16.f32 " \
        "{%0,%1,%2,%3},{%4,%5,%6,%7},{%8,%9},{%0,%1,%2,%3};" \
        : "+f"((c)[0]), "+f"((c)[1]), "+f"((c)[2]), "+f"((c)[3]) \
        : "r"((a)[0]), "r"((a)[1]), "r"((a)[2]), "r"((a)[3]), \
          "r"((b)[0]), "r"((b)[1]))

__device__ __forceinline__ uint32_t h2pack(float a, float b) {
    __half2 h = __floats2half2_rn(a, b);
    return *reinterpret_cast<uint32_t*>(&h);
}

__device__ __forceinline__ float blockReduce256(float v, float* sm) {
    int t = threadIdx.x;
    sm[t] = v;
    __syncthreads();
    #pragma unroll
    for (int off = 128; off > 0; off >>= 1) {
        if (t < off) sm[t] += sm[t + off];
        __syncthreads();
    }
    float r = sm[0];
    __syncthreads();
    return r;
}

// pad-40-halves row layout (80 bytes): ldmatrix phases conflict-free.
#define PADH 40
#define PADB 80

// ================= fused precompute 1 =================
// bid 0: consts; 1..32: pgb partials; 33..544: WqT transpose; 545..608: Ph
__global__ __launch_bounds__(256) void kPre1(const float* __restrict__ gamma,
                                             const float* __restrict__ beta,
                                             const float* __restrict__ phiw,
                                             const float* __restrict__ P,
                                             const float* __restrict__ Wq) {
    int bid = blockIdx.x, t = threadIdx.x;
    if (bid == 0) {
        __shared__ float sm[256];
        float a = 0.f, b = 0.f, c = 0.f;
        for (int j = t; j < Dk; j += 256) { a += gamma[j]; b += beta[j]; }
        for (int j = t; j < Rk; j += 256) { c += phiw[j]; }
        float A = blockReduce256(a, sm);
        float B = blockReduce256(b, sm);
        float C = blockReduce256(c, sm);
        if (t == 0) { g_consts[0] = A; g_consts[1] = B; g_consts[2] = C; }
    } else if (bid <= 32) {
        int chunk = bid - 1;
        float ag = 0.f, ab = 0.f;
        #pragma unroll 4
        for (int j = 0; j < 64; j++) {
            int d = chunk * 64 + j;
            float p = P[(size_t)d * Rk + t];
            ag += gamma[d] * p;
            ab += beta[d] * p;
        }
        g_pgp[chunk * Rk + t] = ag;
        g_pbp[chunk * Rk + t] = ab;
    } else if (bid <= 544) {
        int id = bid - 33;
        int bx = id & 63, by = id >> 6;
        __shared__ float tile[32][33];
        int tx = t & 31, ty8 = t >> 5;
        #pragma unroll
        for (int i = 0; i < 32; i += 8)
            tile[ty8 + i][tx] = Wq[(size_t)(by * 32 + ty8 + i) * Dk + bx * 32 + tx];
        __syncthreads();
        #pragma unroll
        for (int i = 0; i < 32; i += 8)
            g_WqT[(size_t)(bx * 32 + ty8 + i) * Rk + by * 32 + tx] =
                __float2half_rn(tile[tx][ty8 + i]);
    } else {
        int base = (bid - 545) * 8192;
        #pragma unroll
        for (int i = 0; i < 8; i++) {
            int idx = base + i * 1024 + t * 4;
            float4 v = *(const float4*)&P[idx];
            uint2 pk = { h2pack(v.x, v.y), h2pack(v.z, v.w) };
            *(uint2*)&g_Ph[idx] = pk;
        }
    }
}

// ================= kEg: E = C @ dlt (C inline from toep) + pgb2 ================
__global__ __launch_bounds__(256) void kEg(const float* __restrict__ dlt,
                                           const float* __restrict__ toep, int Kc) {
    int bid = blockIdx.x, t = threadIdx.x;
    if (bid == 32) {
        float a = 0.f, b = 0.f;
        #pragma unroll
        for (int c = 0; c < 32; c++) { a += g_pgp[c * Rk + t]; b += g_pbp[c * Rk + t]; }
        g_pg[t] = a;
        g_pb[t] = b;
        return;
    }
    __shared__ float st[256];
    __shared__ float Cs[16][34];
    __shared__ float Ds[16][68];
    if (t < Kc) st[t] = toep[t];
    else if (t < 256) st[t] = 0.f;
    int bx = bid & 3, by = bid >> 2;
    int sBase = by * 32, rBase = bx * 64;
    int ty = t >> 4, tx = t & 15;
    int pad = (Kc - 1) >> 1;
    float acc[2][4] = {};
    __syncthreads();
    for (int k0 = 0; k0 < Rk; k0 += 16) {
        {
            int m = t >> 3, kq = (t & 7) * 2;
            int s = sBase + m;
            int i0 = k0 + kq;
            int idx0 = i0 - s + pad, idx1 = idx0 + 1;
            Cs[kq][m]     = ((unsigned)idx0 < (unsigned)Kc) ? st[idx0] : 0.f;
            Cs[kq + 1][m] = ((unsigned)idx1 < (unsigned)Kc) ? st[idx1] : 0.f;
        }
        {
            int kk = t >> 4, n4 = (t & 15) * 4;
            float4 v = *(const float4*)&dlt[(size_t)(k0 + kk) * Rk + rBase + n4];
            *(float4*)&Ds[kk][n4] = v;
        }
        __syncthreads();
        #pragma unroll
        for (int k = 0; k < 16; k++) {
            float a0 = Cs[k][ty * 2], a1 = Cs[k][ty * 2 + 1];
            float b[4];
            #pragma unroll
            for (int j = 0; j < 4; j++) b[j] = Ds[k][tx * 4 + j];
            #pragma unroll
            for (int j = 0; j < 4; j++) { acc[0][j] += a0 * b[j]; acc[1][j] += a1 * b[j]; }
        }
        __syncthreads();
    }
    #pragma unroll
    for (int i = 0; i < 2; i++) {
        int s = sBase + ty * 2 + i;
        #pragma unroll
        for (int j = 0; j < 4; j++) {
            int r = rBase + tx * 4 + j;
            g_E[(size_t)s * Rk + r] = acc[i][j];
            g_Eh[(size_t)s * Rk + r] = __float2half_rn(acc[i][j]);
        }
    }
}

// ================= kApMMA: BT1[s][d] = fp16(gamma[d] * (Eh @ Ph^T)) + cA/cB =====
#define NTA 8
#define SMA_STAGE 20480
#define SMA_TOTAL 61440

__global__ __launch_bounds__(256) void kApMMA(const float* __restrict__ gamma) {
    extern __shared__ char sma[];
    int bid = blockIdx.x, t = threadIdx.x;
    int w = t >> 5, lane = t & 31;
    if (bid >= 32) {
        int s = (bid - 32) * 8 + w;
        float ca = 0.f, cb = 0.f;
        #pragma unroll
        for (int j = 0; j < 8; j++) {
            int r = lane + 32 * j;
            float e = g_E[(size_t)s * Rk + r];
            ca += g_pg[r] * e;
            cb += g_pb[r] * e;
        }
        #pragma unroll
        for (int o = 16; o > 0; o >>= 1) {
            ca += __shfl_xor_sync(0xffffffffu, ca, o);
            cb += __shfl_xor_sync(0xffffffffu, cb, o);
        }
        if (lane == 0) { g_cA[s] = ca; g_cB[s] = cb; }
        return;
    }
    int g = lane >> 2, tg = lane & 3;
    int rowBase = (bid >> 4) * 128;   // s
    int colBase = (bid & 15) * 128;   // d
    int m0w = (w >> 2) * 64, n0w = (w & 3) * 32;

    uint32_t sBase0 = smem_u32(sma);
    uint32_t aBase = (uint32_t)((m0w + (lane & 15)) * PADB + (lane >> 4) * 16);
    uint32_t bBase = 10240u + (uint32_t)((n0w + (lane & 7) + ((lane >> 4) << 3)) * PADB
                                         + ((lane >> 3) & 1) * 16);

    int lr = t >> 1, h = t & 1;
    const __half* Asrc = g_Eh + (size_t)(rowBase + lr) * Rk + h * 16;
    const __half* Bsrc = g_Ph + (size_t)(colBase + lr) * Rk + h * 16;

    float acc[4][4][4] = {};

    #define GA_ISSUE(st, tt) do { \
        __half* A = (__half*)(sma + (st) * SMA_STAGE); \
        __half* B = (__half*)(sma + (st) * SMA_STAGE + 10240); \
        cp16(A + lr * PADH + h * 16,     Asrc + (tt) * 32); \
        cp16(A + lr * PADH + h * 16 + 8, Asrc + (tt) * 32 + 8); \
        cp16(B + lr * PADH + h * 16,     Bsrc + (tt) * 32); \
        cp16(B + lr * PADH + h * 16 + 8, Bsrc + (tt) * 32 + 8); \
        CP_COMMIT(); \
    } while (0)

    GA_ISSUE(0, 0);
    GA_ISSUE(1, 1);
    CP_WAIT1();
    __syncthreads();

    #pragma unroll 1
    for (int tt = 0; tt < NTA; ++tt) {
        int st = tt % 3;
        uint32_t sb = sBase0 + st * SMA_STAGE;
        #pragma unroll
        for (int ks = 0; ks < 2; ++ks) {
            uint32_t af[4][4], bf[4][2];
            #pragma unroll
            for (int mi = 0; mi < 4; ++mi)
                LDSM4(af[mi][0], af[mi][1], af[mi][2], af[mi][3],
                      sb + aBase + mi * 16 * PADB + ks * 32);
            #pragma unroll
            for (int ni2 = 0; ni2 < 2; ++ni2) {
                uint32_t r0, r1, r2, r3;
                LDSM4(r0, r1, r2, r3, sb + bBase + ni2 * 16 * PADB + ks * 32);
                bf[ni2 * 2][0] = r0; bf[ni2 * 2][1] = r1;
                bf[ni2 * 2 + 1][0] = r2; bf[ni2 * 2 + 1][1] = r3;
            }
            #pragma unroll
            for (int mi = 0; mi < 4; ++mi)
                #pragma unroll
                for (int ni = 0; ni < 4; ++ni)
                    MMAF16(acc[mi][ni], af[mi], bf[ni]);
        }
        if (tt + 2 < NTA) {
            GA_ISSUE((tt + 2) % 3, tt + 2);
            CP_WAIT1();
        } else if (tt + 1 < NTA) {
            CP_WAIT0();
        }
        __syncthreads();
    }

    #pragma unroll
    for (int ni = 0; ni < 4; ++ni) {
        int cg = colBase + n0w + ni * 8 + 2 * tg;
        float ga0 = gamma[cg], ga1 = gamma[cg + 1];
        #pragma unroll
        for (int mi = 0; mi < 4; ++mi) {
            int s1 = rowBase + m0w + mi * 16 + g;
            *(uint32_t*)&g_BT1[(size_t)s1 * Dk + cg] =
                h2pack(ga0 * acc[mi][ni][0], ga1 * acc[mi][ni][1]);
            *(uint32_t*)&g_BT1[(size_t)(s1 + 8) * Dk + cg] =
                h2pack(ga0 * acc[mi][ni][2], ga1 * acc[mi][ni][3]);
        }
    }
}

// G[l] = sigmoid(g_logit[..]) * scale[l]
__global__ void kScale(const float* __restrict__ phib, const float* __restrict__ glog,
                       const int* __restrict__ step_p, int glen) {
    int w = threadIdx.x >> 5, lane = threadIdx.x & 31;
    int l = blockIdx.x * 8 + w;
    const float PI_F = 3.14159274101257324f;
    float base = PI_F * ((float)l + 0.5f);
    float c1 = 0.f, c2 = 0.f;
    #pragma unroll
    for (int j = 0; j < 8; j++) {
        int r = lane + 32 * j;
        c1 += cosf((base * (float)r) / (float)Lk);
        c2 += phib[(size_t)l * Rk + r];
    }
    float c3 = (lane < Bk) ? g_feat[(size_t)lane * Lk + l] : 0.f;
    #pragma unroll
    for (int o = 16; o > 0; o >>= 1) {
        c1 += __shfl_xor_sync(0xffffffffu, c1, o);
        c2 += __shfl_xor_sync(0xffffffffu, c2, o);
        c3 += __shfl_xor_sync(0xffffffffu, c3, o);
    }
    if (lane == 0) {
        int step = *step_p;
        float det_scale = fminf((float)((double)step / 2000.0), 1.0f);
        float scale = det_scale * (c1 / (float)Rk) + (c2 / (float)Rk)
                    + (c3 / (float)Bk) * (g_consts[2] / (float)Rk);
        int gi = l / (Dk / glen);
        float gs = 1.0f / (1.0f + expf(-glog[gi]));
        g_G[l] = gs * scale;
    }
}

// ================= fp16 mma GEMM 1 — 2-CTA/SM version ==========================
// U = (X @ A')*rstd + nmr*cA + cB; M=16384, N=256, K=2048. Tile 128x128, BK=32,
// grid (2,128), 256 thr, launch_bounds(256,2). B: 3-stage cp.async (wait1);
// A: fp32 LDG -> stats -> fp16 STS, double-buffered. Stats duplicated per col-CTA.
#define NT1 64
#define SM1_AS0   0
#define SM1_AS1   10240
#define SM1_BS    20480   // 3 stages x 10240
#define SM1_BST   10240
#define SM1_GAM   51200
#define SM1_RSTD  59392
#define SM1_NMR   59904
#define SM1_TOTAL 60416

__global__ __launch_bounds__(256, 2) void kGemm1MMA(const float* __restrict__ X,
                                                    const float* __restrict__ gamma) {
    extern __shared__ char sm1[];
    __half* As[2] = { (__half*)(sm1 + SM1_AS0), (__half*)(sm1 + SM1_AS1) };
    float* s_gam  = (float*)(sm1 + SM1_GAM);
    float* s_rstd = (float*)(sm1 + SM1_RSTD);
    float* s_nmr  = (float*)(sm1 + SM1_NMR);

    int t = threadIdx.x, w = t >> 5, lane = t & 31, g = lane >> 2, tg = lane & 3;
    int rowBase = blockIdx.y * 128;
    int colBase = blockIdx.x * 128;
    int m0w = (w >> 2) * 64, n0w = (w & 3) * 32;

    for (int i = t; i < Dk / 4; i += 256)
        ((float4*)s_gam)[i] = ((const float4*)gamma)[i];

    uint32_t sA[2] = { smem_u32(As[0]), smem_u32(As[1]) };
    uint32_t sBbase = smem_u32(sm1 + SM1_BS);
    uint32_t aBase = (uint32_t)((m0w + (lane & 15)) * PADB + (lane >> 4) * 16);
    uint32_t bBase = (uint32_t)((n0w + (lane & 7) + ((lane >> 4) << 3)) * PADB
                                + ((lane >> 3) & 1) * 16);

    int lr = t >> 1, h = t & 1;   // 2 thr/row for both A (16 floats) and B (16 halves)
    const float4* Xr = (const float4*)(X + (size_t)(rowBase + lr) * Dk);
    const __half* Bsrc = g_BT1 + (size_t)(colBase + lr) * Dk + h * 16;

    float acc[4][4][4] = {};
    float s0 = 0.f, s20 = 0.f, sg0 = 0.f;

    __syncthreads();  // gamma visible

    #define G1_APROC(st, tt, q) do { \
        _Pragma("unroll") \
        for (int j = 0; j < 4; j++) { \
            float4 gv = ((const float4*)s_gam)[(tt) * 8 + h * 4 + j]; \
            s0  += (q[j].x + q[j].y) + (q[j].z + q[j].w); \
            s20 += q[j].x*q[j].x + q[j].y*q[j].y + q[j].z*q[j].z + q[j].w*q[j].w; \
            sg0 += gv.x*q[j].x + gv.y*q[j].y + gv.z*q[j].z + gv.w*q[j].w; \
        } \
        uint4 p0 = { h2pack(q[0].x,q[0].y), h2pack(q[0].z,q[0].w), \
                     h2pack(q[1].x,q[1].y), h2pack(q[1].z,q[1].w) }; \
        uint4 p1 = { h2pack(q[2].x,q[2].y), h2pack(q[2].z,q[2].w), \
                     h2pack(q[3].x,q[3].y), h2pack(q[3].z,q[3].w) }; \
        *(uint4*)(As[(st)] + lr * PADH + h * 16)     = p0; \
        *(uint4*)(As[(st)] + lr * PADH + h * 16 + 8) = p1; \
    } while (0)

    #define G1_BISSUE(st, tt) do { \
        __half* B = (__half*)(sm1 + SM1_BS + (st) * SM1_BST); \
        const __half* src = Bsrc + (tt) * 32; \
        cp16(B + lr * PADH + h * 16,     src); \
        cp16(B + lr * PADH + h * 16 + 8, src + 8); \
        CP_COMMIT(); \
    } while (0)

    // prologue
    {
        G1_BISSUE(0, 0);
        G1_BISSUE(1, 1);
        float4 q[4];
        #pragma unroll
        for (int j = 0; j < 4; j++) q[j] = Xr[h * 4 + j];
        G1_APROC(0, 0, q);
    }
    CP_WAIT1();
    __syncthreads();

    #pragma unroll 1
    for (int tt = 0; tt < NT1; ++tt) {
        float4 q[4];
        if (tt + 2 < NT1) G1_BISSUE((tt + 2) % 3, tt + 2);
        if (tt + 1 < NT1) {
            int kq = (tt + 1) * 8;
            #pragma unroll
            for (int j = 0; j < 4; j++) q[j] = Xr[kq + h * 4 + j];
        }
        {
            uint32_t sAb = sA[tt & 1];
            uint32_t sBb = sBbase + (tt % 3) * SM1_BST;
            #pragma unroll
            for (int ks = 0; ks < 2; ++ks) {
                uint32_t af[4][4], bf[4][2];
                #pragma unroll
                for (int mi = 0; mi < 4; ++mi)
                    LDSM4(af[mi][0], af[mi][1], af[mi][2], af[mi][3],
                          sAb + aBase + mi * 16 * PADB + ks * 32);
                #pragma unroll
                for (int ni2 = 0; ni2 < 2; ++ni2) {
                    uint32_t r0, r1, r2, r3;
                    LDSM4(r0, r1, r2, r3, sBb + bBase + ni2 * 16 * PADB + ks * 32);
                    bf[ni2 * 2][0] = r0; bf[ni2 * 2][1] = r1;
                    bf[ni2 * 2 + 1][0] = r2; bf[ni2 * 2 + 1][1] = r3;
                }
                #pragma unroll
                for (int mi = 0; mi < 4; ++mi)
                    #pragma unroll
                    for (int ni = 0; ni < 4; ++ni)
                        MMAF16(acc[mi][ni], af[mi], bf[ni]);
            }
        }
        if (tt + 1 < NT1) {
            G1_APROC((tt + 1) & 1, tt + 1, q);
        }
        if (tt + 2 < NT1) { CP_WAIT1(); }
        else if (tt + 1 < NT1) { CP_WAIT0(); }
        __syncthreads();
    }

    // LN stats: 2 staging threads per row
    {
        s0  += __shfl_xor_sync(0xffffffffu, s0, 1);
        s20 += __shfl_xor_sync(0xffffffffu, s20, 1);
        sg0 += __shfl_xor_sync(0xffffffffu, sg0, 1);
        if (h == 0) {
            float C0 = g_consts[0], C1 = g_consts[1];
            float mean = s0 * (1.f / Dk);
            float var = s20 * (1.f / Dk) - mean * mean;
            float rstd = rsqrtf(var + 1e-5f);
            s_rstd[lr] = rstd;
            s_nmr[lr] = -mean * rstd;
            if (blockIdx.x == 0)
                g_feat[rowBase + lr] = (sg0 - mean * C0) * rstd * (1.f / Dk) + C1 * (1.f / Dk);
        }
    }
    __syncthreads();

    // epilogue -> g_U (fp16)
    #pragma unroll
    for (int ni = 0; ni < 4; ++ni) {
        int cg = colBase + n0w + ni * 8 + 2 * tg;
        float ca0 = g_cA[cg], ca1 = g_cA[cg + 1];
        float cb0 = g_cB[cg], cb1 = g_cB[cg + 1];
        #pragma unroll
        for (int mi = 0; mi < 4; ++mi) {
            int r1 = m0w + mi * 16 + g;
            float rs1 = s_rstd[r1], nm1 = s_nmr[r1];
            float rs2 = s_rstd[r1 + 8], nm2 = s_nmr[r1 + 8];
            uint32_t o1 = h2pack(acc[mi][ni][0] * rs1 + nm1 * ca0 + cb0,
                                 acc[mi][ni][1] * rs1 + nm1 * ca1 + cb1);
            uint32_t o2 = h2pack(acc[mi][ni][2] * rs2 + nm2 * ca0 + cb0,
                                 acc[mi][ni][3] * rs2 + nm2 * ca1 + cb1);
            *(uint32_t*)(g_U + (size_t)(rowBase + r1) * Rk + cg) = o1;
            *(uint32_t*)(g_U + (size_t)(rowBase + r1 + 8) * Rk + cg) = o2;
        }
    }
}

// ================= fp16 mma GEMM 2 — R5 version (128-col, 256-thr) ==============
#define NT2 8
#define SM2_STAGE 20480
#define SM2_TOTAL 61440

__global__ __launch_bounds__(256) void kGemm2MMA(const float* __restrict__ bq,
                                                 float* __restrict__ out) {
    extern __shared__ char sm2[];
    int t = threadIdx.x, w = t >> 5, lane = t & 31, g = lane >> 2, tg = lane & 3;
    int rowBase = blockIdx.y * 128, colBase = blockIdx.x * 128;
    int m0w = (w >> 2) * 64, n0w = (w & 3) * 32;

    uint32_t sBase0 = smem_u32(sm2);
    uint32_t aBase = (uint32_t)((m0w + (lane & 15)) * PADB + (lane >> 4) * 16);
    uint32_t bBase = 10240u + (uint32_t)((n0w + (lane & 7) + ((lane >> 4) << 3)) * PADB
                                         + ((lane >> 3) & 1) * 16);

    int lr = t >> 1, h = t & 1;
    const __half* Asrc = g_U + (size_t)(rowBase + lr) * Rk + h * 16;
    const __half* Bsrc = g_WqT + (size_t)(colBase + lr) * Rk + h * 16;

    float acc[4][4][4] = {};

    #define G2_ISSUE(st, tt) do { \
        __half* A = (__half*)(sm2 + (st) * SM2_STAGE); \
        __half* B = (__half*)(sm2 + (st) * SM2_STAGE + 10240); \
        cp16(A + lr * PADH + h * 16,     Asrc + (tt) * 32); \
        cp16(A + lr * PADH + h * 16 + 8, Asrc + (tt) * 32 + 8); \
        cp16(B + lr * PADH + h * 16,     Bsrc + (tt) * 32); \
        cp16(B + lr * PADH + h * 16 + 8, Bsrc + (tt) * 32 + 8); \
        CP_COMMIT(); \
    } while (0)

    G2_ISSUE(0, 0);
    G2_ISSUE(1, 1);
    CP_WAIT1();
    __syncthreads();

    #pragma unroll 1
    for (int tt = 0; tt < NT2; ++tt) {
        int st = tt % 3;
        uint32_t sb = sBase0 + st * SM2_STAGE;
        #pragma unroll
        for (int ks = 0; ks < 2; ++ks) {
            uint32_t af[4][4], bf[4][2];
            #pragma unroll
            for (int mi = 0; mi < 4; ++mi)
                LDSM4(af[mi][0], af[mi][1], af[mi][2], af[mi][3],
                      sb + aBase + mi * 16 * PADB + ks * 32);
            #pragma unroll
            for (int ni2 = 0; ni2 < 2; ++ni2) {
                uint32_t r0, r1, r2, r3;
                LDSM4(r0, r1, r2, r3, sb + bBase + ni2 * 16 * PADB + ks * 32);
                bf[ni2 * 2][0] = r0; bf[ni2 * 2][1] = r1;
                bf[ni2 * 2 + 1][0] = r2; bf[ni2 * 2 + 1][1] = r3;
            }
            #pragma unroll
            for (int mi = 0; mi < 4; ++mi)
                #pragma unroll
                for (int ni = 0; ni < 4; ++ni)
                    MMAF16(acc[mi][ni], af[mi], bf[ni]);
        }
        if (tt + 2 < NT2) {
            G2_ISSUE((tt + 2) % 3, tt + 2);
            CP_WAIT1();
        } else if (tt + 1 < NT2) {
            CP_WAIT0();
        }
        __syncthreads();
    }

    #pragma unroll
    for (int ni = 0; ni < 4; ++ni) {
        int cg = colBase + n0w + ni * 8 + 2 * tg;
        float G0 = g_G[cg], G1 = g_G[cg + 1];
        float q0 = bq[cg], q1 = bq[cg + 1];
        #pragma unroll
        for (int mi = 0; mi < 4; ++mi) {
            int r1 = rowBase + m0w + mi * 16 + g;
            float2 o1, o2;
            o1.x = G0 * (acc[mi][ni][0] + q0);
            o1.y = G1 * (acc[mi][ni][1] + q1);
            o2.x = G0 * (acc[mi][ni][2] + q0);
            o2.y = G1 * (acc[mi][ni][3] + q1);
            *(float2*)&out[(size_t)r1 * Dk + cg] = o1;
            *(float2*)&out[(size_t)(r1 + 8) * Dk + cg] = o2;
        }
    }
}

// ---------------- launch ----------------
extern "C" void kernel_launch(void* const* d_in, const int* in_sizes, int n_in,
                              void* d_out, int out_size) {
    const float* x     = (const float*)d_in[0];
    const float* gamma = (const float*)d_in[1];
    const float* beta  = (const float*)d_in[2];
    const float* P     = (const float*)d_in[3];
    const float* dlt   = (const float*)d_in[4];
    const float* phiw  = (const float*)d_in[5];
    const float* phib  = (const float*)d_in[6];
    const float* toep  = (const float*)d_in[7];
    const float* Wq    = (const float*)d_in[8];
    const float* bq    = (const float*)d_in[9];
    const float* glog  = (const float*)d_in[10];
    const int*   step  = (const int*)d_in[11];
    int Kc   = in_sizes[7];
    int glen = in_sizes[10];

    cudaFuncSetAttribute(kApMMA,    cudaFuncAttributeMaxDynamicSharedMemorySize, SMA_TOTAL);
    cudaFuncSetAttribute(kGemm1MMA, cudaFuncAttributeMaxDynamicSharedMemorySize, SM1_TOTAL);
    cudaFuncSetAttribute(kGemm2MMA, cudaFuncAttributeMaxDynamicSharedMemorySize, SM2_TOTAL);

    kPre1<<<609, 256>>>(gamma, beta, phiw, P, Wq);
    kEg<<<33, 256>>>(dlt, toep, Kc);
    kApMMA<<<64, 256, SMA_TOTAL>>>(gamma);
    kGemm1MMA<<<dim3(2, 128), 256, SM1_TOTAL>>>(x, gamma);
    kScale<<<256, 256>>>(phib, glog, step, glen);
    kGemm2MMA<<<dim3(16, 128), 256, SM2_TOTAL>>>(bq, (float*)d_out);
}

// round 16
// speedup vs baseline: 1.0299x; 1.0299x over previous
#include <cuda_runtime.h>
#include <cuda_fp16.h>
#include <cstdint>
#include <math.h>

#define Bk 8
#define Lk 2048
#define Dk 2048
#define Rk 256
#define BLk (Bk * Lk)   // 16384 rows

// ---------------- device scratch ----------------
static __device__ float g_E[Rk * Rk];                 // E = C @ dlt fp32  (256x256)
static __device__ __half g_Eh[Rk * Rk];               // E fp16
static __device__ __half g_Ph[Dk * Rk];               // P fp16 (d-major, r-contig)
static __device__ __half g_BT1[Rk * Dk];              // A'^T fp16         (256x2048)
static __device__ __half g_WqT[Dk * Rk];              // Wq^T fp16         (2048x256)
static __device__ __half g_U[(size_t)BLk * Rk];       // z_mixed fp16
static __device__ float g_feat[BLk];
static __device__ float g_pg[Rk], g_pb[Rk];
static __device__ float g_cA[Rk], g_cB[Rk];
static __device__ float g_G[Dk];
static __device__ float g_consts[4];
static __device__ float g_pgp[32 * Rk], g_pbp[32 * Rk];

// ---------------- helpers ----------------
__device__ __forceinline__ uint32_t smem_u32(const void* p) {
    uint32_t a;
    asm("{ .reg .u64 t; cvta.to.shared.u64 t, %1; cvt.u32.u64 %0, t; }" : "=r"(a) : "l"(p));
    return a;
}
__device__ __forceinline__ void cp16(void* dst, const void* src) {
    uint32_t d = smem_u32(dst);
    asm volatile("cp.async.cg.shared.global [%0], [%1], 16;" :: "r"(d), "l"(src) : "memory");
}
#define CP_COMMIT() asm volatile("cp.async.commit_group;" ::: "memory")
#define CP_WAIT0()  asm volatile("cp.async.wait_group 0;" ::: "memory")
#define CP_WAIT1()  asm volatile("cp.async.wait_group 1;" ::: "memory")

#define LDSM4(r0, r1, r2, r3, addr) \
    asm volatile("ldmatrix.sync.aligned.m8n8.x4.shared.b16 {%0,%1,%2,%3}, [%4];" \
        : "=r"(r0), "=r"(r1), "=r"(r2), "=r"(r3) : "r"(addr))

#define MMAF16(c, a, b) \
    asm volatile( \
        "mma.sync.aligned.m16n8k16.row.col.f32.f16.f16.f32 " \
        "{%0,%1,%2,%3},{%4,%5,%6,%7},{%8,%9},{%0,%1,%2,%3};" \
        : "+f"((c)[0]), "+f"((c)[1]), "+f"((c)[2]), "+f"((c)[3]) \
        : "r"((a)[0]), "r"((a)[1]), "r"((a)[2]), "r"((a)[3]), \
          "r"((b)[0]), "r"((b)[1]))

__device__ __forceinline__ uint32_t h2pack(float a, float b) {
    __half2 h = __floats2half2_rn(a, b);
    return *reinterpret_cast<uint32_t*>(&h);
}

__device__ __forceinline__ float blockReduce256(float v, float* sm) {
    int t = threadIdx.x;
    sm[t] = v;
    __syncthreads();
    #pragma unroll
    for (int off = 128; off > 0; off >>= 1) {
        if (t < off) sm[t] += sm[t + off];
        __syncthreads();
    }
    float r = sm[0];
    __syncthreads();
    return r;
}

// pad-40-halves row layout (80 bytes): ldmatrix phases conflict-free.
#define PADH 40
#define PADB 80

// ================= fused precompute 1 =================
// bid 0: consts; 1..32: pgb partials; 33..544: WqT transpose; 545..608: Ph
__global__ __launch_bounds__(256) void kPre1(const float* __restrict__ gamma,
                                             const float* __restrict__ beta,
                                             const float* __restrict__ phiw,
                                             const float* __restrict__ P,
                                             const float* __restrict__ Wq) {
    int bid = blockIdx.x, t = threadIdx.x;
    if (bid == 0) {
        __shared__ float sm[256];
        float a = 0.f, b = 0.f, c = 0.f;
        for (int j = t; j < Dk; j += 256) { a += gamma[j]; b += beta[j]; }
        for (int j = t; j < Rk; j += 256) { c += phiw[j]; }
        float A = blockReduce256(a, sm);
        float B = blockReduce256(b, sm);
        float C = blockReduce256(c, sm);
        if (t == 0) { g_consts[0] = A; g_consts[1] = B; g_consts[2] = C; }
    } else if (bid <= 32) {
        int chunk = bid - 1;
        float ag = 0.f, ab = 0.f;
        #pragma unroll 4
        for (int j = 0; j < 64; j++) {
            int d = chunk * 64 + j;
            float p = P[(size_t)d * Rk + t];
            ag += gamma[d] * p;
            ab += beta[d] * p;
        }
        g_pgp[chunk * Rk + t] = ag;
        g_pbp[chunk * Rk + t] = ab;
    } else if (bid <= 544) {
        int id = bid - 33;
        int bx = id & 63, by = id >> 6;
        __shared__ float tile[32][33];
        int tx = t & 31, ty8 = t >> 5;
        #pragma unroll
        for (int i = 0; i < 32; i += 8)
            tile[ty8 + i][tx] = Wq[(size_t)(by * 32 + ty8 + i) * Dk + bx * 32 + tx];
        __syncthreads();
        #pragma unroll
        for (int i = 0; i < 32; i += 8)
            g_WqT[(size_t)(bx * 32 + ty8 + i) * Rk + by * 32 + tx] =
                __float2half_rn(tile[tx][ty8 + i]);
    } else {
        // Ph = fp16(P): 64 blocks x 8192 elems
        int base = (bid - 545) * 8192;
        #pragma unroll
        for (int i = 0; i < 8; i++) {
            int idx = base + i * 1024 + t * 4;
            float4 v = *(const float4*)&P[idx];
            uint2 pk = { h2pack(v.x, v.y), h2pack(v.z, v.w) };
            *(uint2*)&g_Ph[idx] = pk;
        }
    }
}

// ================= kEg: E = C @ dlt (C inline from toep) + pgb2 ================
// 32x64 tiles, grid 33. C[s,i] = toep[i-s+pad] (0 outside range).
__global__ __launch_bounds__(256) void kEg(const float* __restrict__ dlt,
                                           const float* __restrict__ toep, int Kc) {
    int bid = blockIdx.x, t = threadIdx.x;
    if (bid == 32) {
        float a = 0.f, b = 0.f;
        #pragma unroll
        for (int c = 0; c < 32; c++) { a += g_pgp[c * Rk + t]; b += g_pbp[c * Rk + t]; }
        g_pg[t] = a;
        g_pb[t] = b;
        return;
    }
    __shared__ float st[256];
    __shared__ float Cs[16][34];
    __shared__ float Ds[16][68];
    if (t < Kc) st[t] = toep[t];
    else if (t < 256) st[t] = 0.f;
    int bx = bid & 3, by = bid >> 2;
    int sBase = by * 32, rBase = bx * 64;
    int ty = t >> 4, tx = t & 15;
    int pad = (Kc - 1) >> 1;
    float acc[2][4] = {};
    __syncthreads();
    for (int k0 = 0; k0 < Rk; k0 += 16) {
        {
            int m = t >> 3, kq = (t & 7) * 2;
            int s = sBase + m;
            int i0 = k0 + kq;
            int idx0 = i0 - s + pad, idx1 = idx0 + 1;
            Cs[kq][m]     = ((unsigned)idx0 < (unsigned)Kc) ? st[idx0] : 0.f;
            Cs[kq + 1][m] = ((unsigned)idx1 < (unsigned)Kc) ? st[idx1] : 0.f;
        }
        {
            int kk = t >> 4, n4 = (t & 15) * 4;
            float4 v = *(const float4*)&dlt[(size_t)(k0 + kk) * Rk + rBase + n4];
            *(float4*)&Ds[kk][n4] = v;
        }
        __syncthreads();
        #pragma unroll
        for (int k = 0; k < 16; k++) {
            float a0 = Cs[k][ty * 2], a1 = Cs[k][ty * 2 + 1];
            float b[4];
            #pragma unroll
            for (int j = 0; j < 4; j++) b[j] = Ds[k][tx * 4 + j];
            #pragma unroll
            for (int j = 0; j < 4; j++) { acc[0][j] += a0 * b[j]; acc[1][j] += a1 * b[j]; }
        }
        __syncthreads();
    }
    #pragma unroll
    for (int i = 0; i < 2; i++) {
        int s = sBase + ty * 2 + i;
        #pragma unroll
        for (int j = 0; j < 4; j++) {
            int r = rBase + tx * 4 + j;
            g_E[(size_t)s * Rk + r] = acc[i][j];
            g_Eh[(size_t)s * Rk + r] = __float2half_rn(acc[i][j]);
        }
    }
}

// ================= kApMMA: BT1[s][d] = fp16(gamma[d] * (Eh @ Ph^T)) + cA/cB =====
// bid < 32: mma tile. bid 32..63: cA/cB, warp per s (8 s per block).
#define NTA 8
#define SMA_STAGE 20480
#define SMA_TOTAL 61440

__global__ __launch_bounds__(256) void kApMMA(const float* __restrict__ gamma) {
    extern __shared__ char sma[];
    int bid = blockIdx.x, t = threadIdx.x;
    int w = t >> 5, lane = t & 31;
    if (bid >= 32) {
        int s = (bid - 32) * 8 + w;
        float ca = 0.f, cb = 0.f;
        #pragma unroll
        for (int j = 0; j < 8; j++) {
            int r = lane + 32 * j;
            float e = g_E[(size_t)s * Rk + r];
            ca += g_pg[r] * e;
            cb += g_pb[r] * e;
        }
        #pragma unroll
        for (int o = 16; o > 0; o >>= 1) {
            ca += __shfl_xor_sync(0xffffffffu, ca, o);
            cb += __shfl_xor_sync(0xffffffffu, cb, o);
        }
        if (lane == 0) { g_cA[s] = ca; g_cB[s] = cb; }
        return;
    }
    int g = lane >> 2, tg = lane & 3;
    int rowBase = (bid >> 4) * 128;   // s
    int colBase = (bid & 15) * 128;   // d
    int m0w = (w >> 2) * 64, n0w = (w & 3) * 32;

    uint32_t sBase0 = smem_u32(sma);
    uint32_t aBase = (uint32_t)((m0w + (lane & 15)) * PADB + (lane >> 4) * 16);
    uint32_t bBase = 10240u + (uint32_t)((n0w + (lane & 7) + ((lane >> 4) << 3)) * PADB
                                         + ((lane >> 3) & 1) * 16);

    int lr = t >> 1, h = t & 1;
    const __half* Asrc = g_Eh + (size_t)(rowBase + lr) * Rk + h * 16;
    const __half* Bsrc = g_Ph + (size_t)(colBase + lr) * Rk + h * 16;

    float acc[4][4][4] = {};

    #define GA_ISSUE(st, tt) do { \
        __half* A = (__half*)(sma + (st) * SMA_STAGE); \
        __half* B = (__half*)(sma + (st) * SMA_STAGE + 10240); \
        cp16(A + lr * PADH + h * 16,     Asrc + (tt) * 32); \
        cp16(A + lr * PADH + h * 16 + 8, Asrc + (tt) * 32 + 8); \
        cp16(B + lr * PADH + h * 16,     Bsrc + (tt) * 32); \
        cp16(B + lr * PADH + h * 16 + 8, Bsrc + (tt) * 32 + 8); \
        CP_COMMIT(); \
    } while (0)

    GA_ISSUE(0, 0);
    GA_ISSUE(1, 1);
    CP_WAIT1();
    __syncthreads();

    #pragma unroll 1
    for (int tt = 0; tt < NTA; ++tt) {
        int st = tt % 3;
        uint32_t sb = sBase0 + st * SMA_STAGE;
        #pragma unroll
        for (int ks = 0; ks < 2; ++ks) {
            uint32_t af[4][4], bf[4][2];
            #pragma unroll
            for (int mi = 0; mi < 4; ++mi)
                LDSM4(af[mi][0], af[mi][1], af[mi][2], af[mi][3],
                      sb + aBase + mi * 16 * PADB + ks * 32);
            #pragma unroll
            for (int ni2 = 0; ni2 < 2; ++ni2) {
                uint32_t r0, r1, r2, r3;
                LDSM4(r0, r1, r2, r3, sb + bBase + ni2 * 16 * PADB + ks * 32);
                bf[ni2 * 2][0] = r0; bf[ni2 * 2][1] = r1;
                bf[ni2 * 2 + 1][0] = r2; bf[ni2 * 2 + 1][1] = r3;
            }
            #pragma unroll
            for (int mi = 0; mi < 4; ++mi)
                #pragma unroll
                for (int ni = 0; ni < 4; ++ni)
                    MMAF16(acc[mi][ni], af[mi], bf[ni]);
        }
        if (tt + 2 < NTA) {
            GA_ISSUE((tt + 2) % 3, tt + 2);
            CP_WAIT1();
        } else if (tt + 1 < NTA) {
            CP_WAIT0();
        }
        __syncthreads();
    }

    #pragma unroll
    for (int ni = 0; ni < 4; ++ni) {
        int cg = colBase + n0w + ni * 8 + 2 * tg;
        float ga0 = gamma[cg], ga1 = gamma[cg + 1];
        #pragma unroll
        for (int mi = 0; mi < 4; ++mi) {
            int s1 = rowBase + m0w + mi * 16 + g;
            *(uint32_t*)&g_BT1[(size_t)s1 * Dk + cg] =
                h2pack(ga0 * acc[mi][ni][0], ga1 * acc[mi][ni][1]);
            *(uint32_t*)&g_BT1[(size_t)(s1 + 8) * Dk + cg] =
                h2pack(ga0 * acc[mi][ni][2], ga1 * acc[mi][ni][3]);
        }
    }
}

// G[l] = sigmoid(g_logit[..]) * scale[l]  (needs g_feat from GEMM1)
__global__ void kScale(const float* __restrict__ phib, const float* __restrict__ glog,
                       const int* __restrict__ step_p, int glen) {
    int w = threadIdx.x >> 5, lane = threadIdx.x & 31;
    int l = blockIdx.x * 8 + w;
    const float PI_F = 3.14159274101257324f;
    float base = PI_F * ((float)l + 0.5f);
    float c1 = 0.f, c2 = 0.f;
    #pragma unroll
    for (int j = 0; j < 8; j++) {
        int r = lane + 32 * j;
        c1 += cosf((base * (float)r) / (float)Lk);
        c2 += phib[(size_t)l * Rk + r];
    }
    float c3 = (lane < Bk) ? g_feat[(size_t)lane * Lk + l] : 0.f;
    #pragma unroll
    for (int o = 16; o > 0; o >>= 1) {
        c1 += __shfl_xor_sync(0xffffffffu, c1, o);
        c2 += __shfl_xor_sync(0xffffffffu, c2, o);
        c3 += __shfl_xor_sync(0xffffffffu, c3, o);
    }
    if (lane == 0) {
        int step = *step_p;
        float det_scale = fminf((float)((double)step / 2000.0), 1.0f);
        float scale = det_scale * (c1 / (float)Rk) + (c2 / (float)Rk)
                    + (c3 / (float)Bk) * (g_consts[2] / (float)Rk);
        int gi = l / (Dk / glen);
        float gs = 1.0f / (1.0f + expf(-glog[gi]));
        g_G[l] = gs * scale;
    }
}

// ================= fp16 mma GEMM 1 — R13/R14 version (measured floor) ===========
#define NT1 64
#define SM1_AS0   0
#define SM1_AS1   10240
#define SM1_BS    20480   // 3 stages x 20480
#define SM1_BST   20480
#define SM1_GAM   81920
#define SM1_RSTD  90112
#define SM1_NMR   90624
#define SM1_TOTAL 91136

__global__ __launch_bounds__(512) void kGemm1MMA(const float* __restrict__ X,
                                                 const float* __restrict__ gamma) {
    extern __shared__ char sm1[];
    __half* As[2] = { (__half*)(sm1 + SM1_AS0), (__half*)(sm1 + SM1_AS1) };
    float* s_gam  = (float*)(sm1 + SM1_GAM);
    float* s_rstd = (float*)(sm1 + SM1_RSTD);
    float* s_nmr  = (float*)(sm1 + SM1_NMR);

    int t = threadIdx.x, w = t >> 5, lane = t & 31, g = lane >> 2, tg = lane & 3;
    int rowBase = blockIdx.x * 128;
    int m0w = (w >> 3) * 64, n0w = (w & 7) * 32;

    for (int i = t; i < Dk / 4; i += 512)
        ((float4*)s_gam)[i] = ((const float4*)gamma)[i];

    uint32_t sA[2] = { smem_u32(As[0]), smem_u32(As[1]) };
    uint32_t sBbase = smem_u32(sm1 + SM1_BS);
    uint32_t aBase = (uint32_t)((m0w + (lane & 15)) * PADB + (lane >> 4) * 16);
    uint32_t bBase = (uint32_t)((n0w + (lane & 7) + ((lane >> 4) << 3)) * PADB
                                + ((lane >> 3) & 1) * 16);

    int lr = t >> 1, h = t & 1;   // A stagers: row (0..127), 16-float half
    int t2 = t & 255;             // B stagers row
    const float4* Xr = (const float4*)(X + (size_t)(rowBase + lr) * Dk);
    const __half* Bsrc = g_BT1 + (size_t)t2 * Dk;

    float acc[4][4][4] = {};
    float s0 = 0.f, s20 = 0.f, sg0 = 0.f;

    __syncthreads();  // gamma visible

    #define G1_APROC(st, tt, q) do { \
        _Pragma("unroll") \
        for (int j = 0; j < 4; j++) { \
            float4 gv = ((const float4*)s_gam)[(tt) * 8 + h * 4 + j]; \
            s0  += (q[j].x + q[j].y) + (q[j].z + q[j].w); \
            s20 += q[j].x*q[j].x + q[j].y*q[j].y + q[j].z*q[j].z + q[j].w*q[j].w; \
            sg0 += gv.x*q[j].x + gv.y*q[j].y + gv.z*q[j].z + gv.w*q[j].w; \
        } \
        uint4 p0 = { h2pack(q[0].x,q[0].y), h2pack(q[0].z,q[0].w), \
                     h2pack(q[1].x,q[1].y), h2pack(q[1].z,q[1].w) }; \
        uint4 p1 = { h2pack(q[2].x,q[2].y), h2pack(q[2].z,q[2].w), \
                     h2pack(q[3].x,q[3].y), h2pack(q[3].z,q[3].w) }; \
        *(uint4*)(As[(st)] + lr * PADH + h * 16)     = p0; \
        *(uint4*)(As[(st)] + lr * PADH + h * 16 + 8) = p1; \
    } while (0)

    #define G1_BISSUE(st, tt) do { \
        __half* B = (__half*)(sm1 + SM1_BS + (st) * SM1_BST); \
        const __half* src = Bsrc + (tt) * 32; \
        cp16(B + t2 * PADH + 0,  src); \
        cp16(B + t2 * PADH + 8,  src + 8); \
        cp16(B + t2 * PADH + 16, src + 16); \
        cp16(B + t2 * PADH + 24, src + 24); \
        CP_COMMIT(); \
    } while (0)

    // prologue: A tile0 -> As[0]; B tiles 0,1 -> stages 0,1
    if (t >= 256) {
        G1_BISSUE(0, 0);
        G1_BISSUE(1, 1);
    } else {
        float4 q[4];
        #pragma unroll
        for (int j = 0; j < 4; j++) q[j] = Xr[h * 4 + j];
        G1_APROC(0, 0, q);
    }
    CP_WAIT1();
    __syncthreads();

    #pragma unroll 1
    for (int tt = 0; tt < NT1; ++tt) {
        float4 q[4];
        if (t >= 256) {
            if (tt + 2 < NT1) G1_BISSUE((tt + 2) % 3, tt + 2);
        } else if (tt + 1 < NT1) {
            int kq = (tt + 1) * 8;
            #pragma unroll
            for (int j = 0; j < 4; j++) q[j] = Xr[kq + h * 4 + j];
        }
        {
            uint32_t sAb = sA[tt & 1];
            uint32_t sBb = sBbase + (tt % 3) * SM1_BST;
            #pragma unroll
            for (int ks = 0; ks < 2; ++ks) {
                uint32_t af[4][4], bf[4][2];
                #pragma unroll
                for (int mi = 0; mi < 4; ++mi)
                    LDSM4(af[mi][0], af[mi][1], af[mi][2], af[mi][3],
                          sAb + aBase + mi * 16 * PADB + ks * 32);
                #pragma unroll
                for (int ni2 = 0; ni2 < 2; ++ni2) {
                    uint32_t r0, r1, r2, r3;
                    LDSM4(r0, r1, r2, r3, sBb + bBase + ni2 * 16 * PADB + ks * 32);
                    bf[ni2 * 2][0] = r0; bf[ni2 * 2][1] = r1;
                    bf[ni2 * 2 + 1][0] = r2; bf[ni2 * 2 + 1][1] = r3;
                }
                #pragma unroll
                for (int mi = 0; mi < 4; ++mi)
                    #pragma unroll
                    for (int ni = 0; ni < 4; ++ni)
                        MMAF16(acc[mi][ni], af[mi], bf[ni]);
            }
        }
        if (tt + 1 < NT1 && t < 256) {
            G1_APROC((tt + 1) & 1, tt + 1, q);
        }
        if (tt + 2 < NT1) { CP_WAIT1(); }
        else if (tt + 1 < NT1) { CP_WAIT0(); }
        __syncthreads();
    }

    // LN stats: 2 staging threads per row
    if (t < 256) {
        s0  += __shfl_xor_sync(0xffffffffu, s0, 1);
        s20 += __shfl_xor_sync(0xffffffffu, s20, 1);
        sg0 += __shfl_xor_sync(0xffffffffu, sg0, 1);
        if (h == 0) {
            float C0 = g_consts[0], C1 = g_consts[1];
            float mean = s0 * (1.f / Dk);
            float var = s20 * (1.f / Dk) - mean * mean;
            float rstd = rsqrtf(var + 1e-5f);
            s_rstd[lr] = rstd;
            s_nmr[lr] = -mean * rstd;
            g_feat[rowBase + lr] = (sg0 - mean * C0) * rstd * (1.f / Dk) + C1 * (1.f / Dk);
        }
    }
    __syncthreads();

    // epilogue -> g_U (fp16)
    #pragma unroll
    for (int ni = 0; ni < 4; ++ni) {
        int cg = n0w + ni * 8 + 2 * tg;
        float ca0 = g_cA[cg], ca1 = g_cA[cg + 1];
        float cb0 = g_cB[cg], cb1 = g_cB[cg + 1];
        #pragma unroll
        for (int mi = 0; mi < 4; ++mi) {
            int r1 = m0w + mi * 16 + g;
            float rs1 = s_rstd[r1], nm1 = s_nmr[r1];
            float rs2 = s_rstd[r1 + 8], nm2 = s_nmr[r1 + 8];
            uint32_t o1 = h2pack(acc[mi][ni][0] * rs1 + nm1 * ca0 + cb0,
                                 acc[mi][ni][1] * rs1 + nm1 * ca1 + cb1);
            uint32_t o2 = h2pack(acc[mi][ni][2] * rs2 + nm2 * ca0 + cb0,
                                 acc[mi][ni][3] * rs2 + nm2 * ca1 + cb1);
            *(uint32_t*)(g_U + (size_t)(rowBase + r1) * Rk + cg) = o1;
            *(uint32_t*)(g_U + (size_t)(rowBase + r1 + 8) * Rk + cg) = o2;
        }
    }
}

// ================= fp16 mma GEMM 2 — R5 version (128-col, 256-thr) ==============
#define NT2 8
#define SM2_STAGE 20480
#define SM2_TOTAL 61440

__global__ __launch_bounds__(256) void kGemm2MMA(const float* __restrict__ bq,
                                                 float* __restrict__ out) {
    extern __shared__ char sm2[];
    int t = threadIdx.x, w = t >> 5, lane = t & 31, g = lane >> 2, tg = lane & 3;
    int rowBase = blockIdx.y * 128, colBase = blockIdx.x * 128;
    int m0w = (w >> 2) * 64, n0w = (w & 3) * 32;

    uint32_t sBase0 = smem_u32(sm2);
    uint32_t aBase = (uint32_t)((m0w + (lane & 15)) * PADB + (lane >> 4) * 16);
    uint32_t bBase = 10240u + (uint32_t)((n0w + (lane & 7) + ((lane >> 4) << 3)) * PADB
                                         + ((lane >> 3) & 1) * 16);

    int lr = t >> 1, h = t & 1;
    const __half* Asrc = g_U + (size_t)(rowBase + lr) * Rk + h * 16;
    const __half* Bsrc = g_WqT + (size_t)(colBase + lr) * Rk + h * 16;

    float acc[4][4][4] = {};

    #define G2_ISSUE(st, tt) do { \
        __half* A = (__half*)(sm2 + (st) * SM2_STAGE); \
        __half* B = (__half*)(sm2 + (st) * SM2_STAGE + 10240); \
        cp16(A + lr * PADH + h * 16,     Asrc + (tt) * 32); \
        cp16(A + lr * PADH + h * 16 + 8, Asrc + (tt) * 32 + 8); \
        cp16(B + lr * PADH + h * 16,     Bsrc + (tt) * 32); \
        cp16(B + lr * PADH + h * 16 + 8, Bsrc + (tt) * 32 + 8); \
        CP_COMMIT(); \
    } while (0)

    G2_ISSUE(0, 0);
    G2_ISSUE(1, 1);
    CP_WAIT1();
    __syncthreads();

    #pragma unroll 1
    for (int tt = 0; tt < NT2; ++tt) {
        int st = tt % 3;
        uint32_t sb = sBase0 + st * SM2_STAGE;
        #pragma unroll
        for (int ks = 0; ks < 2; ++ks) {
            uint32_t af[4][4], bf[4][2];
            #pragma unroll
            for (int mi = 0; mi < 4; ++mi)
                LDSM4(af[mi][0], af[mi][1], af[mi][2], af[mi][3],
                      sb + aBase + mi * 16 * PADB + ks * 32);
            #pragma unroll
            for (int ni2 = 0; ni2 < 2; ++ni2) {
                uint32_t r0, r1, r2, r3;
                LDSM4(r0, r1, r2, r3, sb + bBase + ni2 * 16 * PADB + ks * 32);
                bf[ni2 * 2][0] = r0; bf[ni2 * 2][1] = r1;
                bf[ni2 * 2 + 1][0] = r2; bf[ni2 * 2 + 1][1] = r3;
            }
            #pragma unroll
            for (int mi = 0; mi < 4; ++mi)
                #pragma unroll
                for (int ni = 0; ni < 4; ++ni)
                    MMAF16(acc[mi][ni], af[mi], bf[ni]);
        }
        if (tt + 2 < NT2) {
            G2_ISSUE((tt + 2) % 3, tt + 2);
            CP_WAIT1();
        } else if (tt + 1 < NT2) {
            CP_WAIT0();
        }
        __syncthreads();
    }

    #pragma unroll
    for (int ni = 0; ni < 4; ++ni) {
        int cg = colBase + n0w + ni * 8 + 2 * tg;
        float G0 = g_G[cg], G1 = g_G[cg + 1];
        float q0 = bq[cg], q1 = bq[cg + 1];
        #pragma unroll
        for (int mi = 0; mi < 4; ++mi) {
            int r1 = rowBase + m0w + mi * 16 + g;
            float2 o1, o2;
            o1.x = G0 * (acc[mi][ni][0] + q0);
            o1.y = G1 * (acc[mi][ni][1] + q1);
            o2.x = G0 * (acc[mi][ni][2] + q0);
            o2.y = G1 * (acc[mi][ni][3] + q1);
            *(float2*)&out[(size_t)r1 * Dk + cg] = o1;
            *(float2*)&out[(size_t)(r1 + 8) * Dk + cg] = o2;
        }
    }
}

// ---------------- launch ----------------
extern "C" void kernel_launch(void* const* d_in, const int* in_sizes, int n_in,
                              void* d_out, int out_size) {
    const float* x     = (const float*)d_in[0];
    const float* gamma = (const float*)d_in[1];
    const float* beta  = (const float*)d_in[2];
    const float* P     = (const float*)d_in[3];
    const float* dlt   = (const float*)d_in[4];
    const float* phiw  = (const float*)d_in[5];
    const float* phib  = (const float*)d_in[6];
    const float* toep  = (const float*)d_in[7];
    const float* Wq    = (const float*)d_in[8];
    const float* bq    = (const float*)d_in[9];
    const float* glog  = (const float*)d_in[10];
    const int*   step  = (const int*)d_in[11];
    int Kc   = in_sizes[7];
    int glen = in_sizes[10];

    cudaFuncSetAttribute(kApMMA,    cudaFuncAttributeMaxDynamicSharedMemorySize, SMA_TOTAL);
    cudaFuncSetAttribute(kGemm1MMA, cudaFuncAttributeMaxDynamicSharedMemorySize, SM1_TOTAL);
    cudaFuncSetAttribute(kGemm2MMA, cudaFuncAttributeMaxDynamicSharedMemorySize, SM2_TOTAL);

    kPre1<<<609, 256>>>(gamma, beta, phiw, P, Wq);
    kEg<<<33, 256>>>(dlt, toep, Kc);
    kApMMA<<<64, 256, SMA_TOTAL>>>(gamma);
    kGemm1MMA<<<128, 512, SM1_TOTAL>>>(x, gamma);
    kScale<<<256, 256>>>(phib, glog, step, glen);
    kGemm2MMA<<<dim3(16, 128), 256, SM2_TOTAL>>>(bq, (float*)d_out);
}

// round 17
// speedup vs baseline: 1.0514x; 1.0208x over previous
#include <cuda_runtime.h>
#include <cuda_fp16.h>
#include <cstdint>
#include <math.h>

#define Bk 8
#define Lk 2048
#define Dk 2048
#define Rk 256
#define BLk (Bk * Lk)   // 16384 rows

// ---------------- device scratch ----------------
static __device__ float g_E[Rk * Rk];                 // E = C @ dlt fp32  (256x256)
static __device__ __half g_Eh[Rk * Rk];               // E fp16
static __device__ __half g_Ph[Dk * Rk];               // P fp16 (d-major, r-contig)
static __device__ __half g_BT1[Rk * Dk];              // A'^T fp16         (256x2048)
static __device__ __half g_WqT[Dk * Rk];              // Wq^T fp16         (2048x256)
static __device__ __half g_U[(size_t)BLk * Rk];       // z_mixed fp16
static __device__ float g_feat[BLk];
static __device__ float g_pg[Rk], g_pb[Rk];
static __device__ float g_cA[Rk], g_cB[Rk];
static __device__ float g_G[Dk];                      // final gate*scale
static __device__ float g_Gpre[Dk];                   // det*sdet + pbm
static __device__ float g_Gs[Dk];                     // sigmoid(g_logit[..])
static __device__ float g_consts[4];
static __device__ float g_pgp[32 * Rk], g_pbp[32 * Rk];

// ---------------- helpers ----------------
__device__ __forceinline__ uint32_t smem_u32(const void* p) {
    uint32_t a;
    asm("{ .reg .u64 t; cvta.to.shared.u64 t, %1; cvt.u32.u64 %0, t; }" : "=r"(a) : "l"(p));
    return a;
}
__device__ __forceinline__ void cp16(void* dst, const void* src) {
    uint32_t d = smem_u32(dst);
    asm volatile("cp.async.cg.shared.global [%0], [%1], 16;" :: "r"(d), "l"(src) : "memory");
}
#define CP_COMMIT() asm volatile("cp.async.commit_group;" ::: "memory")
#define CP_WAIT0()  asm volatile("cp.async.wait_group 0;" ::: "memory")
#define CP_WAIT1()  asm volatile("cp.async.wait_group 1;" ::: "memory")

#define LDSM4(r0, r1, r2, r3, addr) \
    asm volatile("ldmatrix.sync.aligned.m8n8.x4.shared.b16 {%0,%1,%2,%3}, [%4];" \
        : "=r"(r0), "=r"(r1), "=r"(r2), "=r"(r3) : "r"(addr))

#define MMAF16(c, a, b) \
    asm volatile( \
        "mma.sync.aligned.m16n8k16.row.col.f32.f16.f16.f32 " \
        "{%0,%1,%2,%3},{%4,%5,%6,%7},{%8,%9},{%0,%1,%2,%3};" \
        : "+f"((c)[0]), "+f"((c)[1]), "+f"((c)[2]), "+f"((c)[3]) \
        : "r"((a)[0]), "r"((a)[1]), "r"((a)[2]), "r"((a)[3]), \
          "r"((b)[0]), "r"((b)[1]))

__device__ __forceinline__ uint32_t h2pack(float a, float b) {
    __half2 h = __floats2half2_rn(a, b);
    return *reinterpret_cast<uint32_t*>(&h);
}

__device__ __forceinline__ float blockReduce256(float v, float* sm) {
    int t = threadIdx.x;
    sm[t] = v;
    __syncthreads();
    #pragma unroll
    for (int off = 128; off > 0; off >>= 1) {
        if (t < off) sm[t] += sm[t + off];
        __syncthreads();
    }
    float r = sm[0];
    __syncthreads();
    return r;
}

// pad-40-halves row layout (80 bytes): ldmatrix phases conflict-free.
#define PADH 40
#define PADB 80

// ================= fused precompute 1 =================
// bid 0: consts; 1..32: pgb partials; 33..544: WqT transpose; 545..608: Ph
__global__ __launch_bounds__(256) void kPre1(const float* __restrict__ gamma,
                                             const float* __restrict__ beta,
                                             const float* __restrict__ phiw,
                                             const float* __restrict__ P,
                                             const float* __restrict__ Wq) {
    int bid = blockIdx.x, t = threadIdx.x;
    if (bid == 0) {
        __shared__ float sm[256];
        float a = 0.f, b = 0.f, c = 0.f;
        for (int j = t; j < Dk; j += 256) { a += gamma[j]; b += beta[j]; }
        for (int j = t; j < Rk; j += 256) { c += phiw[j]; }
        float A = blockReduce256(a, sm);
        float B = blockReduce256(b, sm);
        float C = blockReduce256(c, sm);
        if (t == 0) { g_consts[0] = A; g_consts[1] = B; g_consts[2] = C; }
    } else if (bid <= 32) {
        int chunk = bid - 1;
        float ag = 0.f, ab = 0.f;
        #pragma unroll 4
        for (int j = 0; j < 64; j++) {
            int d = chunk * 64 + j;
            float p = P[(size_t)d * Rk + t];
            ag += gamma[d] * p;
            ab += beta[d] * p;
        }
        g_pgp[chunk * Rk + t] = ag;
        g_pbp[chunk * Rk + t] = ab;
    } else if (bid <= 544) {
        int id = bid - 33;
        int bx = id & 63, by = id >> 6;
        __shared__ float tile[32][33];
        int tx = t & 31, ty8 = t >> 5;
        #pragma unroll
        for (int i = 0; i < 32; i += 8)
            tile[ty8 + i][tx] = Wq[(size_t)(by * 32 + ty8 + i) * Dk + bx * 32 + tx];
        __syncthreads();
        #pragma unroll
        for (int i = 0; i < 32; i += 8)
            g_WqT[(size_t)(bx * 32 + ty8 + i) * Rk + by * 32 + tx] =
                __float2half_rn(tile[tx][ty8 + i]);
    } else {
        // Ph = fp16(P): 64 blocks x 8192 elems
        int base = (bid - 545) * 8192;
        #pragma unroll
        for (int i = 0; i < 8; i++) {
            int idx = base + i * 1024 + t * 4;
            float4 v = *(const float4*)&P[idx];
            uint2 pk = { h2pack(v.x, v.y), h2pack(v.z, v.w) };
            *(uint2*)&g_Ph[idx] = pk;
        }
    }
}

// ================= kEg: E = C @ dlt (C inline from toep) + pgb2 ================
__global__ __launch_bounds__(256) void kEg(const float* __restrict__ dlt,
                                           const float* __restrict__ toep, int Kc) {
    int bid = blockIdx.x, t = threadIdx.x;
    if (bid == 32) {
        float a = 0.f, b = 0.f;
        #pragma unroll
        for (int c = 0; c < 32; c++) { a += g_pgp[c * Rk + t]; b += g_pbp[c * Rk + t]; }
        g_pg[t] = a;
        g_pb[t] = b;
        return;
    }
    __shared__ float st[256];
    __shared__ float Cs[16][34];
    __shared__ float Ds[16][68];
    if (t < Kc) st[t] = toep[t];
    else if (t < 256) st[t] = 0.f;
    int bx = bid & 3, by = bid >> 2;
    int sBase = by * 32, rBase = bx * 64;
    int ty = t >> 4, tx = t & 15;
    int pad = (Kc - 1) >> 1;
    float acc[2][4] = {};
    __syncthreads();
    for (int k0 = 0; k0 < Rk; k0 += 16) {
        {
            int m = t >> 3, kq = (t & 7) * 2;
            int s = sBase + m;
            int i0 = k0 + kq;
            int idx0 = i0 - s + pad, idx1 = idx0 + 1;
            Cs[kq][m]     = ((unsigned)idx0 < (unsigned)Kc) ? st[idx0] : 0.f;
            Cs[kq + 1][m] = ((unsigned)idx1 < (unsigned)Kc) ? st[idx1] : 0.f;
        }
        {
            int kk = t >> 4, n4 = (t & 15) * 4;
            float4 v = *(const float4*)&dlt[(size_t)(k0 + kk) * Rk + rBase + n4];
            *(float4*)&Ds[kk][n4] = v;
        }
        __syncthreads();
        #pragma unroll
        for (int k = 0; k < 16; k++) {
            float a0 = Cs[k][ty * 2], a1 = Cs[k][ty * 2 + 1];
            float b[4];
            #pragma unroll
            for (int j = 0; j < 4; j++) b[j] = Ds[k][tx * 4 + j];
            #pragma unroll
            for (int j = 0; j < 4; j++) { acc[0][j] += a0 * b[j]; acc[1][j] += a1 * b[j]; }
        }
        __syncthreads();
    }
    #pragma unroll
    for (int i = 0; i < 2; i++) {
        int s = sBase + ty * 2 + i;
        #pragma unroll
        for (int j = 0; j < 4; j++) {
            int r = rBase + tx * 4 + j;
            g_E[(size_t)s * Rk + r] = acc[i][j];
            g_Eh[(size_t)s * Rk + r] = __float2half_rn(acc[i][j]);
        }
    }
}

// ================= kApMMA: BT1 mma + cA/cB + scale-pre (free blocks) ============
// bid < 32: mma tile. bid 32..63: cA/cB (warp per s). bid 64..319: scale-pre for
// l = (bid-64)*8 + warp: g_Gpre[l] = det*sdet + pbm, g_Gs[l] = sigmoid(glog[..]).
#define NTA 8
#define SMA_STAGE 20480
#define SMA_TOTAL 61440

__global__ __launch_bounds__(256) void kApMMA(const float* __restrict__ gamma,
                                              const float* __restrict__ phib,
                                              const float* __restrict__ glog,
                                              const int* __restrict__ step_p,
                                              int glen) {
    extern __shared__ char sma[];
    int bid = blockIdx.x, t = threadIdx.x;
    int w = t >> 5, lane = t & 31;
    if (bid >= 64) {
        // scale-pre: feat-independent part of scale[l]
        int l = (bid - 64) * 8 + w;
        const float PI_F = 3.14159274101257324f;
        float base = PI_F * ((float)l + 0.5f);
        float c1 = 0.f, c2 = 0.f;
        #pragma unroll
        for (int j = 0; j < 8; j++) {
            int r = lane + 32 * j;
            c1 += cosf((base * (float)r) / (float)Lk);
            c2 += phib[(size_t)l * Rk + r];
        }
        #pragma unroll
        for (int o = 16; o > 0; o >>= 1) {
            c1 += __shfl_xor_sync(0xffffffffu, c1, o);
            c2 += __shfl_xor_sync(0xffffffffu, c2, o);
        }
        if (lane == 0) {
            int step = *step_p;
            float det_scale = fminf((float)((double)step / 2000.0), 1.0f);
            g_Gpre[l] = det_scale * (c1 / (float)Rk) + (c2 / (float)Rk);
            int gi = l / (Dk / glen);
            g_Gs[l] = 1.0f / (1.0f + expf(-glog[gi]));
        }
        return;
    }
    if (bid >= 32) {
        int s = (bid - 32) * 8 + w;
        float ca = 0.f, cb = 0.f;
        #pragma unroll
        for (int j = 0; j < 8; j++) {
            int r = lane + 32 * j;
            float e = g_E[(size_t)s * Rk + r];
            ca += g_pg[r] * e;
            cb += g_pb[r] * e;
        }
        #pragma unroll
        for (int o = 16; o > 0; o >>= 1) {
            ca += __shfl_xor_sync(0xffffffffu, ca, o);
            cb += __shfl_xor_sync(0xffffffffu, cb, o);
        }
        if (lane == 0) { g_cA[s] = ca; g_cB[s] = cb; }
        return;
    }
    int g = lane >> 2, tg = lane & 3;
    int rowBase = (bid >> 4) * 128;   // s
    int colBase = (bid & 15) * 128;   // d
    int m0w = (w >> 2) * 64, n0w = (w & 3) * 32;

    uint32_t sBase0 = smem_u32(sma);
    uint32_t aBase = (uint32_t)((m0w + (lane & 15)) * PADB + (lane >> 4) * 16);
    uint32_t bBase = 10240u + (uint32_t)((n0w + (lane & 7) + ((lane >> 4) << 3)) * PADB
                                         + ((lane >> 3) & 1) * 16);

    int lr = t >> 1, h = t & 1;
    const __half* Asrc = g_Eh + (size_t)(rowBase + lr) * Rk + h * 16;
    const __half* Bsrc = g_Ph + (size_t)(colBase + lr) * Rk + h * 16;

    float acc[4][4][4] = {};

    #define GA_ISSUE(st, tt) do { \
        __half* A = (__half*)(sma + (st) * SMA_STAGE); \
        __half* B = (__half*)(sma + (st) * SMA_STAGE + 10240); \
        cp16(A + lr * PADH + h * 16,     Asrc + (tt) * 32); \
        cp16(A + lr * PADH + h * 16 + 8, Asrc + (tt) * 32 + 8); \
        cp16(B + lr * PADH + h * 16,     Bsrc + (tt) * 32); \
        cp16(B + lr * PADH + h * 16 + 8, Bsrc + (tt) * 32 + 8); \
        CP_COMMIT(); \
    } while (0)

    GA_ISSUE(0, 0);
    GA_ISSUE(1, 1);
    CP_WAIT1();
    __syncthreads();

    #pragma unroll 1
    for (int tt = 0; tt < NTA; ++tt) {
        int st = tt % 3;
        uint32_t sb = sBase0 + st * SMA_STAGE;
        #pragma unroll
        for (int ks = 0; ks < 2; ++ks) {
            uint32_t af[4][4], bf[4][2];
            #pragma unroll
            for (int mi = 0; mi < 4; ++mi)
                LDSM4(af[mi][0], af[mi][1], af[mi][2], af[mi][3],
                      sb + aBase + mi * 16 * PADB + ks * 32);
            #pragma unroll
            for (int ni2 = 0; ni2 < 2; ++ni2) {
                uint32_t r0, r1, r2, r3;
                LDSM4(r0, r1, r2, r3, sb + bBase + ni2 * 16 * PADB + ks * 32);
                bf[ni2 * 2][0] = r0; bf[ni2 * 2][1] = r1;
                bf[ni2 * 2 + 1][0] = r2; bf[ni2 * 2 + 1][1] = r3;
            }
            #pragma unroll
            for (int mi = 0; mi < 4; ++mi)
                #pragma unroll
                for (int ni = 0; ni < 4; ++ni)
                    MMAF16(acc[mi][ni], af[mi], bf[ni]);
        }
        if (tt + 2 < NTA) {
            GA_ISSUE((tt + 2) % 3, tt + 2);
            CP_WAIT1();
        } else if (tt + 1 < NTA) {
            CP_WAIT0();
        }
        __syncthreads();
    }

    #pragma unroll
    for (int ni = 0; ni < 4; ++ni) {
        int cg = colBase + n0w + ni * 8 + 2 * tg;
        float ga0 = gamma[cg], ga1 = gamma[cg + 1];
        #pragma unroll
        for (int mi = 0; mi < 4; ++mi) {
            int s1 = rowBase + m0w + mi * 16 + g;
            *(uint32_t*)&g_BT1[(size_t)s1 * Dk + cg] =
                h2pack(ga0 * acc[mi][ni][0], ga1 * acc[mi][ni][1]);
            *(uint32_t*)&g_BT1[(size_t)(s1 + 8) * Dk + cg] =
                h2pack(ga0 * acc[mi][ni][2], ga1 * acc[mi][ni][3]);
        }
    }
}

// ================= kScaleB: G[l] = gs[l] * (pre[l] + fbar[l]*wbar) ==============
// Tiny post-GEMM1 kernel. grid 8, 256 thr; thread handles one l.
__global__ void kScaleB() {
    int l = blockIdx.x * 256 + threadIdx.x;
    float fs = 0.f;
    #pragma unroll
    for (int b = 0; b < Bk; b++) fs += g_feat[(size_t)b * Lk + l];
    float wbar = g_consts[2] / (float)Rk;
    g_G[l] = g_Gs[l] * (g_Gpre[l] + (fs / (float)Bk) * wbar);
}

// ================= fp16 mma GEMM 1 — R13/R14 version (measured floor) ===========
#define NT1 64
#define SM1_AS0   0
#define SM1_AS1   10240
#define SM1_BS    20480   // 3 stages x 20480
#define SM1_BST   20480
#define SM1_GAM   81920
#define SM1_RSTD  90112
#define SM1_NMR   90624
#define SM1_TOTAL 91136

__global__ __launch_bounds__(512) void kGemm1MMA(const float* __restrict__ X,
                                                 const float* __restrict__ gamma) {
    extern __shared__ char sm1[];
    __half* As[2] = { (__half*)(sm1 + SM1_AS0), (__half*)(sm1 + SM1_AS1) };
    float* s_gam  = (float*)(sm1 + SM1_GAM);
    float* s_rstd = (float*)(sm1 + SM1_RSTD);
    float* s_nmr  = (float*)(sm1 + SM1_NMR);

    int t = threadIdx.x, w = t >> 5, lane = t & 31, g = lane >> 2, tg = lane & 3;
    int rowBase = blockIdx.x * 128;
    int m0w = (w >> 3) * 64, n0w = (w & 7) * 32;

    for (int i = t; i < Dk / 4; i += 512)
        ((float4*)s_gam)[i] = ((const float4*)gamma)[i];

    uint32_t sA[2] = { smem_u32(As[0]), smem_u32(As[1]) };
    uint32_t sBbase = smem_u32(sm1 + SM1_BS);
    uint32_t aBase = (uint32_t)((m0w + (lane & 15)) * PADB + (lane >> 4) * 16);
    uint32_t bBase = (uint32_t)((n0w + (lane & 7) + ((lane >> 4) << 3)) * PADB
                                + ((lane >> 3) & 1) * 16);

    int lr = t >> 1, h = t & 1;   // A stagers: row (0..127), 16-float half
    int t2 = t & 255;             // B stagers row
    const float4* Xr = (const float4*)(X + (size_t)(rowBase + lr) * Dk);
    const __half* Bsrc = g_BT1 + (size_t)t2 * Dk;

    float acc[4][4][4] = {};
    float s0 = 0.f, s20 = 0.f, sg0 = 0.f;

    __syncthreads();  // gamma visible

    #define G1_APROC(st, tt, q) do { \
        _Pragma("unroll") \
        for (int j = 0; j < 4; j++) { \
            float4 gv = ((const float4*)s_gam)[(tt) * 8 + h * 4 + j]; \
            s0  += (q[j].x + q[j].y) + (q[j].z + q[j].w); \
            s20 += q[j].x*q[j].x + q[j].y*q[j].y + q[j].z*q[j].z + q[j].w*q[j].w; \
            sg0 += gv.x*q[j].x + gv.y*q[j].y + gv.z*q[j].z + gv.w*q[j].w; \
        } \
        uint4 p0 = { h2pack(q[0].x,q[0].y), h2pack(q[0].z,q[0].w), \
                     h2pack(q[1].x,q[1].y), h2pack(q[1].z,q[1].w) }; \
        uint4 p1 = { h2pack(q[2].x,q[2].y), h2pack(q[2].z,q[2].w), \
                     h2pack(q[3].x,q[3].y), h2pack(q[3].z,q[3].w) }; \
        *(uint4*)(As[(st)] + lr * PADH + h * 16)     = p0; \
        *(uint4*)(As[(st)] + lr * PADH + h * 16 + 8) = p1; \
    } while (0)

    #define G1_BISSUE(st, tt) do { \
        __half* B = (__half*)(sm1 + SM1_BS + (st) * SM1_BST); \
        const __half* src = Bsrc + (tt) * 32; \
        cp16(B + t2 * PADH + 0,  src); \
        cp16(B + t2 * PADH + 8,  src + 8); \
        cp16(B + t2 * PADH + 16, src + 16); \
        cp16(B + t2 * PADH + 24, src + 24); \
        CP_COMMIT(); \
    } while (0)

    // prologue: A tile0 -> As[0]; B tiles 0,1 -> stages 0,1
    if (t >= 256) {
        G1_BISSUE(0, 0);
        G1_BISSUE(1, 1);
    } else {
        float4 q[4];
        #pragma unroll
        for (int j = 0; j < 4; j++) q[j] = Xr[h * 4 + j];
        G1_APROC(0, 0, q);
    }
    CP_WAIT1();
    __syncthreads();

    #pragma unroll 1
    for (int tt = 0; tt < NT1; ++tt) {
        float4 q[4];
        if (t >= 256) {
            if (tt + 2 < NT1) G1_BISSUE((tt + 2) % 3, tt + 2);
        } else if (tt + 1 < NT1) {
            int kq = (tt + 1) * 8;
            #pragma unroll
            for (int j = 0; j < 4; j++) q[j] = Xr[kq + h * 4 + j];
        }
        {
            uint32_t sAb = sA[tt & 1];
            uint32_t sBb = sBbase + (tt % 3) * SM1_BST;
            #pragma unroll
            for (int ks = 0; ks < 2; ++ks) {
                uint32_t af[4][4], bf[4][2];
                #pragma unroll
                for (int mi = 0; mi < 4; ++mi)
                    LDSM4(af[mi][0], af[mi][1], af[mi][2], af[mi][3],
                          sAb + aBase + mi * 16 * PADB + ks * 32);
                #pragma unroll
                for (int ni2 = 0; ni2 < 2; ++ni2) {
                    uint32_t r0, r1, r2, r3;
                    LDSM4(r0, r1, r2, r3, sBb + bBase + ni2 * 16 * PADB + ks * 32);
                    bf[ni2 * 2][0] = r0; bf[ni2 * 2][1] = r1;
                    bf[ni2 * 2 + 1][0] = r2; bf[ni2 * 2 + 1][1] = r3;
                }
                #pragma unroll
                for (int mi = 0; mi < 4; ++mi)
                    #pragma unroll
                    for (int ni = 0; ni < 4; ++ni)
                        MMAF16(acc[mi][ni], af[mi], bf[ni]);
            }
        }
        if (tt + 1 < NT1 && t < 256) {
            G1_APROC((tt + 1) & 1, tt + 1, q);
        }
        if (tt + 2 < NT1) { CP_WAIT1(); }
        else if (tt + 1 < NT1) { CP_WAIT0(); }
        __syncthreads();
    }

    // LN stats: 2 staging threads per row
    if (t < 256) {
        s0  += __shfl_xor_sync(0xffffffffu, s0, 1);
        s20 += __shfl_xor_sync(0xffffffffu, s20, 1);
        sg0 += __shfl_xor_sync(0xffffffffu, sg0, 1);
        if (h == 0) {
            float C0 = g_consts[0], C1 = g_consts[1];
            float mean = s0 * (1.f / Dk);
            float var = s20 * (1.f / Dk) - mean * mean;
            float rstd = rsqrtf(var + 1e-5f);
            s_rstd[lr] = rstd;
            s_nmr[lr] = -mean * rstd;
            g_feat[rowBase + lr] = (sg0 - mean * C0) * rstd * (1.f / Dk) + C1 * (1.f / Dk);
        }
    }
    __syncthreads();

    // epilogue -> g_U (fp16)
    #pragma unroll
    for (int ni = 0; ni < 4; ++ni) {
        int cg = n0w + ni * 8 + 2 * tg;
        float ca0 = g_cA[cg], ca1 = g_cA[cg + 1];
        float cb0 = g_cB[cg], cb1 = g_cB[cg + 1];
        #pragma unroll
        for (int mi = 0; mi < 4; ++mi) {
            int r1 = m0w + mi * 16 + g;
            float rs1 = s_rstd[r1], nm1 = s_nmr[r1];
            float rs2 = s_rstd[r1 + 8], nm2 = s_nmr[r1 + 8];
            uint32_t o1 = h2pack(acc[mi][ni][0] * rs1 + nm1 * ca0 + cb0,
                                 acc[mi][ni][1] * rs1 + nm1 * ca1 + cb1);
            uint32_t o2 = h2pack(acc[mi][ni][2] * rs2 + nm2 * ca0 + cb0,
                                 acc[mi][ni][3] * rs2 + nm2 * ca1 + cb1);
            *(uint32_t*)(g_U + (size_t)(rowBase + r1) * Rk + cg) = o1;
            *(uint32_t*)(g_U + (size_t)(rowBase + r1 + 8) * Rk + cg) = o2;
        }
    }
}

// ================= fp16 mma GEMM 2 — R5 version (128-col, 256-thr) ==============
#define NT2 8
#define SM2_STAGE 20480
#define SM2_TOTAL 61440

__global__ __launch_bounds__(256) void kGemm2MMA(const float* __restrict__ bq,
                                                 float* __restrict__ out) {
    extern __shared__ char sm2[];
    int t = threadIdx.x, w = t >> 5, lane = t & 31, g = lane >> 2, tg = lane & 3;
    int rowBase = blockIdx.y * 128, colBase = blockIdx.x * 128;
    int m0w = (w >> 2) * 64, n0w = (w & 3) * 32;

    uint32_t sBase0 = smem_u32(sm2);
    uint32_t aBase = (uint32_t)((m0w + (lane & 15)) * PADB + (lane >> 4) * 16);
    uint32_t bBase = 10240u + (uint32_t)((n0w + (lane & 7) + ((lane >> 4) << 3)) * PADB
                                         + ((lane >> 3) & 1) * 16);

    int lr = t >> 1, h = t & 1;
    const __half* Asrc = g_U + (size_t)(rowBase + lr) * Rk + h * 16;
    const __half* Bsrc = g_WqT + (size_t)(colBase + lr) * Rk + h * 16;

    float acc[4][4][4] = {};

    #define G2_ISSUE(st, tt) do { \
        __half* A = (__half*)(sm2 + (st) * SM2_STAGE); \
        __half* B = (__half*)(sm2 + (st) * SM2_STAGE + 10240); \
        cp16(A + lr * PADH + h * 16,     Asrc + (tt) * 32); \
        cp16(A + lr * PADH + h * 16 + 8, Asrc + (tt) * 32 + 8); \
        cp16(B + lr * PADH + h * 16,     Bsrc + (tt) * 32); \
        cp16(B + lr * PADH + h * 16 + 8, Bsrc + (tt) * 32 + 8); \
        CP_COMMIT(); \
    } while (0)

    G2_ISSUE(0, 0);
    G2_ISSUE(1, 1);
    CP_WAIT1();
    __syncthreads();

    #pragma unroll 1
    for (int tt = 0; tt < NT2; ++tt) {
        int st = tt % 3;
        uint32_t sb = sBase0 + st * SM2_STAGE;
        #pragma unroll
        for (int ks = 0; ks < 2; ++ks) {
            uint32_t af[4][4], bf[4][2];
            #pragma unroll
            for (int mi = 0; mi < 4; ++mi)
                LDSM4(af[mi][0], af[mi][1], af[mi][2], af[mi][3],
                      sb + aBase + mi * 16 * PADB + ks * 32);
            #pragma unroll
            for (int ni2 = 0; ni2 < 2; ++ni2) {
                uint32_t r0, r1, r2, r3;
                LDSM4(r0, r1, r2, r3, sb + bBase + ni2 * 16 * PADB + ks * 32);
                bf[ni2 * 2][0] = r0; bf[ni2 * 2][1] = r1;
                bf[ni2 * 2 + 1][0] = r2; bf[ni2 * 2 + 1][1] = r3;
            }
            #pragma unroll
            for (int mi = 0; mi < 4; ++mi)
                #pragma unroll
                for (int ni = 0; ni < 4; ++ni)
                    MMAF16(acc[mi][ni], af[mi], bf[ni]);
        }
        if (tt + 2 < NT2) {
            G2_ISSUE((tt + 2) % 3, tt + 2);
            CP_WAIT1();
        } else if (tt + 1 < NT2) {
            CP_WAIT0();
        }
        __syncthreads();
    }

    #pragma unroll
    for (int ni = 0; ni < 4; ++ni) {
        int cg = colBase + n0w + ni * 8 + 2 * tg;
        float G0 = g_G[cg], G1 = g_G[cg + 1];
        float q0 = bq[cg], q1 = bq[cg + 1];
        #pragma unroll
        for (int mi = 0; mi < 4; ++mi) {
            int r1 = rowBase + m0w + mi * 16 + g;
            float2 o1, o2;
            o1.x = G0 * (acc[mi][ni][0] + q0);
            o1.y = G1 * (acc[mi][ni][1] + q1);
            o2.x = G0 * (acc[mi][ni][2] + q0);
            o2.y = G1 * (acc[mi][ni][3] + q1);
            *(float2*)&out[(size_t)r1 * Dk + cg] = o1;
            *(float2*)&out[(size_t)(r1 + 8) * Dk + cg] = o2;
        }
    }
}

// ---------------- launch ----------------
extern "C" void kernel_launch(void* const* d_in, const int* in_sizes, int n_in,
                              void* d_out, int out_size) {
    const float* x     = (const float*)d_in[0];
    const float* gamma = (const float*)d_in[1];
    const float* beta  = (const float*)d_in[2];
    const float* P     = (const float*)d_in[3];
    const float* dlt   = (const float*)d_in[4];
    const float* phiw  = (const float*)d_in[5];
    const float* phib  = (const float*)d_in[6];
    const float* toep  = (const float*)d_in[7];
    const float* Wq    = (const float*)d_in[8];
    const float* bq    = (const float*)d_in[9];
    const float* glog  = (const float*)d_in[10];
    const int*   step  = (const int*)d_in[11];
    int Kc   = in_sizes[7];
    int glen = in_sizes[10];

    cudaFuncSetAttribute(kApMMA,    cudaFuncAttributeMaxDynamicSharedMemorySize, SMA_TOTAL);
    cudaFuncSetAttribute(kGemm1MMA, cudaFuncAttributeMaxDynamicSharedMemorySize, SM1_TOTAL);
    cudaFuncSetAttribute(kGemm2MMA, cudaFuncAttributeMaxDynamicSharedMemorySize, SM2_TOTAL);

    kPre1<<<609, 256>>>(gamma, beta, phiw, P, Wq);
    kEg<<<33, 256>>>(dlt, toep, Kc);
    kApMMA<<<320, 256, SMA_TOTAL>>>(gamma, phib, glog, step, glen);
    kGemm1MMA<<<128, 512, SM1_TOTAL>>>(x, gamma);
    kScaleB<<<8, 256>>>();
    kGemm2MMA<<<dim3(16, 128), 256, SM2_TOTAL>>>(bq, (float*)d_out);
}